// round 15
// baseline (speedup 1.0000x reference)
#include <cuda_runtime.h>
#include <cuda_fp16.h>
#include <cstdint>

#define DD 128
#define NMAX 100000
#define EMAX 3200000
#define EPS 1e-5f
#define SCAN_B 1024
#define MAXPARTS 128
#define NSM 148
#define MT 64          // rows per GEMM tile
#define WP16 136       // Ws pitch in uints (half2): 8t+g bank pattern
#define AP16 132       // As pitch in uints (half2): 4g+t bank pattern

// ---------------- scratch (no cudaMalloc allowed) ----------------
__device__ __align__(16) __half g_h16[(size_t)NMAX * DD];
__device__ __align__(16) __half g_n16[(size_t)NMAX * DD];
__device__ int g_esrc[EMAX];
__device__ int g_rank[EMAX];      // packed: (rank << 17) | dst
__device__ int g_cnt[NMAX];
__device__ int g_off[NMAX + 1];   // per-block local inclusive scan
__device__ int g_part[MAXPARTS];  // exclusive scan of block sums
__device__ float g_sum[DD];
__device__ float g_sumsq[DD];
__device__ int g_is64;

// global exclusive offset of node d (no scan3 pass needed)
__device__ __forceinline__ int off_ex(int d) {
    return (d == 0) ? 0 : (g_off[d] + g_part[(d - 1) >> 10]);
}

__device__ __forceinline__ void mma_f16(float* c, const unsigned* a, unsigned b0, unsigned b1) {
    asm volatile("mma.sync.aligned.m16n8k16.row.col.f32.f16.f16.f32 "
                 "{%0,%1,%2,%3}, {%4,%5,%6,%7}, {%8,%9}, {%0,%1,%2,%3};"
                 : "+f"(c[0]), "+f"(c[1]), "+f"(c[2]), "+f"(c[3])
                 : "r"(a[0]), "r"(a[1]), "r"(a[2]), "r"(a[3]), "r"(b0), "r"(b1));
}

// ---------------- dtype probe + zero counters ----------------
__global__ void k_detect(const int* __restrict__ s, const int* __restrict__ d, int e, int n) {
    int tid = blockIdx.x * blockDim.x + threadIdx.x;
    int nt = gridDim.x * blockDim.x;
    if (tid == 0) {
        int m = e < 64 ? e : 64;
        int odd = 0;
        for (int i = 0; i < m; i++) odd |= s[2 * i + 1] | d[2 * i + 1];
        g_is64 = (odd == 0) ? 1 : 0;
    }
    for (int i = tid; i < n; i += nt) g_cnt[i] = 0;
    if (tid < DD) { g_sum[tid] = 0.f; g_sumsq[tid] = 0.f; }
}

// ---------------- h -> fp16 mirror (side branch) ----------------
__global__ void k_h2h(const float* __restrict__ h, int n) {
    int tid = blockIdx.x * blockDim.x + threadIdx.x;
    int nt = gridDim.x * blockDim.x;
    int total = n * (DD / 4);
    for (int i = tid; i < total; i += nt) {
        float4 v = ((const float4*)h)[i];
        __half2 a = __floats2half2_rn(v.x, v.y);
        __half2 b = __floats2half2_rn(v.z, v.w);
        uint2 u;
        u.x = *(unsigned*)&a;
        u.y = *(unsigned*)&b;
        ((uint2*)g_h16)[i] = u;
    }
}

// ---------------- histogram + packed (rank|dst), 2 edges/thread ----------------
__global__ void k_hist(const int* __restrict__ dst, int e, int n) {
    int i = 2 * (blockIdx.x * blockDim.x + threadIdx.x);
    if (i >= e) return;
    int d0, d1 = -1;
    bool two = (i + 1 < e);
    if (g_is64) {
        int4 v = ((const int4*)dst)[i >> 1];   // edges i (x,y) and i+1 (z,w)
        d0 = v.x; if (two) d1 = v.z;
    } else {
        int2 v = ((const int2*)dst)[i >> 1];
        d0 = v.x; if (two) d1 = v.y;
    }
    int r0 = 0, r1 = 0;
    if ((unsigned)d0 < (unsigned)n) r0 = atomicAdd(&g_cnt[d0], 1);
    if (two && (unsigned)d1 < (unsigned)n) r1 = atomicAdd(&g_cnt[d1], 1);
    g_rank[i] = (r0 << 17) | (d0 & 0x1FFFF);
    if (two) g_rank[i + 1] = (r1 << 17) | (d1 & 0x1FFFF);
}

// ---------------- decoupled scan (2 phases; carry folded into consumers) ------
__global__ void __launch_bounds__(SCAN_B) k_scan1(int n) {
    __shared__ int sdata[SCAN_B];
    int tid = threadIdx.x;
    int i = blockIdx.x * SCAN_B + tid;
    int v = (i < n) ? g_cnt[i] : 0;
    sdata[tid] = v;
    __syncthreads();
    #pragma unroll
    for (int off = 1; off < SCAN_B; off <<= 1) {
        int t = (tid >= off) ? sdata[tid - off] : 0;
        __syncthreads();
        sdata[tid] += t;
        __syncthreads();
    }
    if (i < n) g_off[i + 1] = sdata[tid];   // local inclusive of element i
    if (tid == SCAN_B - 1) g_part[blockIdx.x] = sdata[tid];
}

__global__ void __launch_bounds__(MAXPARTS) k_scan2(int nblocks) {
    __shared__ int sdata[MAXPARTS];
    int tid = threadIdx.x;
    int v = (tid < nblocks) ? g_part[tid] : 0;
    sdata[tid] = v;
    __syncthreads();
    #pragma unroll
    for (int off = 1; off < MAXPARTS; off <<= 1) {
        int t = (tid >= off) ? sdata[tid - off] : 0;
        __syncthreads();
        sdata[tid] += t;
        __syncthreads();
    }
    if (tid < nblocks) g_part[tid] = sdata[tid] - v;   // exclusive
}

// ---------------- bucket fill (atomic-free, packed rank, 2 edges/thread) ------
__global__ void k_fill(const int* __restrict__ src, int e, int n) {
    int i = 2 * (blockIdx.x * blockDim.x + threadIdx.x);
    if (i >= e) return;
    int s0, s1 = -1;
    bool two = (i + 1 < e);
    if (g_is64) {
        int4 v = ((const int4*)src)[i >> 1];
        s0 = v.x; if (two) s1 = v.z;
    } else {
        int2 v = ((const int2*)src)[i >> 1];
        s0 = v.x; if (two) s1 = v.y;
    }
    int p0 = g_rank[i];
    int d0 = p0 & 0x1FFFF, r0 = (unsigned)p0 >> 17;
    if ((unsigned)d0 < (unsigned)n && (unsigned)s0 < (unsigned)n) {
        int pos = off_ex(d0) + r0;
        if ((unsigned)pos < (unsigned)EMAX) g_esrc[pos] = s0;
    }
    if (two) {
        int p1 = g_rank[i + 1];
        int d1 = p1 & 0x1FFFF, r1 = (unsigned)p1 >> 17;
        if ((unsigned)d1 < (unsigned)n && (unsigned)s1 < (unsigned)n) {
            int pos = off_ex(d1) + r1;
            if ((unsigned)pos < (unsigned)EMAX) g_esrc[pos] = s1;
        }
    }
}

// ---------------- warp-per-node gather (fp16 rows) -> fp16 neigh ----------------
__global__ void k_gather(int n) {
    int gw = (blockIdx.x * blockDim.x + threadIdx.x) >> 5;
    int lane = threadIdx.x & 31;
    if (gw >= n) return;
    int o0 = off_ex(gw), o1 = off_ex(gw + 1);
    int lane16 = lane & 15, half = lane >> 4;
    const uint4* h4 = (const uint4*)g_h16;   // 16B = 8 halves; 16 uint4 per row
    float acc[8];
    #pragma unroll
    for (int j = 0; j < 8; j++) acc[j] = 0.f;

    for (int jb = o0; jb < o1; jb += 32) {
        int myv = (jb + lane < o1) ? g_esrc[jb + lane] : 0;
        int cnt = min(32, o1 - jb);
        int k = 0;
        #pragma unroll 8
        for (; k + 2 <= cnt; k += 2) {
            int s = __shfl_sync(0xffffffffu, myv, k + half);
            uint4 raw = h4[s * 16 + lane16];
            const __half2* hp = (const __half2*)&raw;
            #pragma unroll
            for (int q = 0; q < 4; q++) {
                float2 f = __half22float2(hp[q]);
                acc[2 * q]     += f.x;
                acc[2 * q + 1] += f.y;
            }
        }
        if (k < cnt) {
            int s = __shfl_sync(0xffffffffu, myv, k);
            if (half == 0) {
                uint4 raw = h4[s * 16 + lane16];
                const __half2* hp = (const __half2*)&raw;
                #pragma unroll
                for (int q = 0; q < 4; q++) {
                    float2 f = __half22float2(hp[q]);
                    acc[2 * q]     += f.x;
                    acc[2 * q + 1] += f.y;
                }
            }
        }
    }

    #pragma unroll
    for (int j = 0; j < 8; j++)
        acc[j] += __shfl_xor_sync(0xffffffffu, acc[j], 16);

    if (half == 0) {
        float inv = 1.0f / fmaxf((float)(o1 - o0), 1.0f);
        uint4 o;
        __half2 p0 = __floats2half2_rn(acc[0] * inv, acc[1] * inv);
        __half2 p1 = __floats2half2_rn(acc[2] * inv, acc[3] * inv);
        __half2 p2 = __floats2half2_rn(acc[4] * inv, acc[5] * inv);
        __half2 p3 = __floats2half2_rn(acc[6] * inv, acc[7] * inv);
        o.x = *(unsigned*)&p0; o.y = *(unsigned*)&p1;
        o.z = *(unsigned*)&p2; o.w = *(unsigned*)&p3;
        ((uint4*)g_n16)[gw * 16 + lane16] = o;
    }
}

// ---------------- fp16 tensor-core dual-GEMM + bias + relu + BN sums ----------------
__global__ void __launch_bounds__(256) k_gemm_tc(
    const float* __restrict__ Wself, const float* __restrict__ Wneigh,
    const float* __restrict__ bias, float* __restrict__ out, int n, int ntiles)
{
    extern __shared__ unsigned smu[];
    unsigned* Wsu = smu;                 // 128 * WP16 uints (half2)
    unsigned* Asu = smu + 128 * WP16;    // MT * AP16 uints (half2)
    int tid = threadIdx.x;
    int wid = tid >> 5, lane = tid & 31;
    int g = lane >> 2, t = lane & 3;
    int wm = wid & 1, wn = wid >> 1;
    int colb = wn * 32;

    for (int i = tid; i < 128 * DD; i += 256) {
        int k2 = i >> 7, col = i & 127;
        int k = 2 * k2;
        const float* w0 = (k < DD) ? (Wself + k * DD) : (Wneigh + (k - DD) * DD);
        const float* w1 = w0 + DD;
        __half2 p = __floats2half2_rn(w0[col], w1[col]);
        Wsu[k2 * WP16 + col] = *(unsigned*)&p;
    }

    float bs[4][2];
    #pragma unroll
    for (int j = 0; j < 4; j++) {
        bs[j][0] = bias[colb + j * 8 + 2 * t];
        bs[j][1] = bias[colb + j * 8 + 2 * t + 1];
    }
    float csum[4][2] = {{0.f,0.f},{0.f,0.f},{0.f,0.f},{0.f,0.f}};
    float csq [4][2] = {{0.f,0.f},{0.f,0.f},{0.f,0.f},{0.f,0.f}};

    const uint4* h4 = (const uint4*)g_h16;
    const uint4* n4 = (const uint4*)g_n16;

    for (int tile = blockIdx.x; tile < ntiles; tile += gridDim.x) {
        int m0 = tile * MT;
        __syncthreads();
        #pragma unroll
        for (int it = 0; it < 8; it++) {
            int q = tid + it * 256;
            int row = q >> 5, c4 = q & 31;
            int rg = m0 + row;
            uint4 v = make_uint4(0u, 0u, 0u, 0u);
            if (rg < n)
                v = (c4 < 16) ? h4[rg * 16 + c4] : n4[rg * 16 + (c4 - 16)];
            *(uint4*)&Asu[row * AP16 + c4 * 4] = v;
        }
        __syncthreads();

        float acc[2][4][4];
        #pragma unroll
        for (int i = 0; i < 2; i++)
            #pragma unroll
            for (int j = 0; j < 4; j++)
                #pragma unroll
                for (int q = 0; q < 4; q++) acc[i][j][q] = 0.f;

        #pragma unroll 4
        for (int kc = 0; kc < 16; kc++) {
            int k2b = kc * 8;
            unsigned a[2][4];
            #pragma unroll
            for (int i = 0; i < 2; i++) {
                int rb = (wm * 32 + i * 16 + g) * AP16 + k2b + t;
                a[i][0] = Asu[rb];
                a[i][1] = Asu[rb + 8 * AP16];
                a[i][2] = Asu[rb + 4];
                a[i][3] = Asu[rb + 8 * AP16 + 4];
            }
            #pragma unroll
            for (int j = 0; j < 4; j++) {
                int col = colb + j * 8 + g;
                unsigned b0 = Wsu[(k2b + t) * WP16 + col];
                unsigned b1 = Wsu[(k2b + 4 + t) * WP16 + col];
                mma_f16(acc[0][j], a[0], b0, b1);
                mma_f16(acc[1][j], a[1], b0, b1);
            }
        }

        #pragma unroll
        for (int i = 0; i < 2; i++) {
            int row0 = m0 + wm * 32 + i * 16 + g;
            #pragma unroll
            for (int j = 0; j < 4; j++) {
                int col = colb + j * 8 + 2 * t;
                float c0 = fmaxf(acc[i][j][0] + bs[j][0], 0.f);
                float c1 = fmaxf(acc[i][j][1] + bs[j][1], 0.f);
                float c2 = fmaxf(acc[i][j][2] + bs[j][0], 0.f);
                float c3 = fmaxf(acc[i][j][3] + bs[j][1], 0.f);
                if (row0 < n) {
                    *(float2*)&out[(size_t)row0 * DD + col] = make_float2(c0, c1);
                    csum[j][0] += c0; csq[j][0] += c0 * c0;
                    csum[j][1] += c1; csq[j][1] += c1 * c1;
                }
                if (row0 + 8 < n) {
                    *(float2*)&out[(size_t)(row0 + 8) * DD + col] = make_float2(c2, c3);
                    csum[j][0] += c2; csq[j][0] += c2 * c2;
                    csum[j][1] += c3; csq[j][1] += c3 * c3;
                }
            }
        }
    }

    #pragma unroll
    for (int j = 0; j < 4; j++)
        #pragma unroll
        for (int p = 0; p < 2; p++) {
            float s = csum[j][p], q = csq[j][p];
            #pragma unroll
            for (int off = 16; off >= 4; off >>= 1) {
                s += __shfl_down_sync(0xffffffffu, s, off);
                q += __shfl_down_sync(0xffffffffu, q, off);
            }
            if (g == 0) {
                int col = colb + j * 8 + 2 * t + p;
                atomicAdd(&g_sum[col], s);
                atomicAdd(&g_sumsq[col], q);
            }
        }
}

// ---------------- normalize + residual (stats computed inline) ----------------
__global__ void k_final(const float* __restrict__ h, const float* __restrict__ gamma,
                        const float* __restrict__ beta, float* __restrict__ out,
                        int n, float inv_n) {
    int i = blockIdx.x * blockDim.x + threadIdx.x;
    int total = n * (DD / 4);
    if (i >= total) return;
    int j4 = i & 31;
    float4 su = ((const float4*)g_sum)[j4];
    float4 sq = ((const float4*)g_sumsq)[j4];
    float4 mu, rs;
    mu.x = su.x * inv_n; mu.y = su.y * inv_n; mu.z = su.z * inv_n; mu.w = su.w * inv_n;
    rs.x = rsqrtf(sq.x * inv_n - mu.x * mu.x + EPS);
    rs.y = rsqrtf(sq.y * inv_n - mu.y * mu.y + EPS);
    rs.z = rsqrtf(sq.z * inv_n - mu.z * mu.z + EPS);
    rs.w = rsqrtf(sq.w * inv_n - mu.w * mu.w + EPS);
    float4 v  = ((float4*)out)[i];
    float4 hv = ((const float4*)h)[i];
    float4 ga = ((const float4*)gamma)[j4];
    float4 be = ((const float4*)beta)[j4];
    v.x = hv.x + (v.x - mu.x) * rs.x * ga.x + be.x;
    v.y = hv.y + (v.y - mu.y) * rs.y * ga.y + be.y;
    v.z = hv.z + (v.z - mu.z) * rs.z * ga.z + be.z;
    v.w = hv.w + (v.w - mu.w) * rs.w * ga.w + be.w;
    ((float4*)out)[i] = v;
}

// ---------------- launch ----------------
extern "C" void kernel_launch(void* const* d_in, const int* in_sizes, int n_in,
                              void* d_out, int out_size) {
    const float* h     = (const float*)d_in[0];
    const int*   src   = (const int*)d_in[1];
    const int*   dst   = (const int*)d_in[2];
    const float* Wself = (const float*)d_in[3];
    const float* Wneigh= (const float*)d_in[4];
    const float* bias  = (const float*)d_in[5];
    const float* gamma = (const float*)d_in[6];
    const float* beta  = (const float*)d_in[7];
    float* out = (float*)d_out;
    int n = in_sizes[0] / DD;
    int e = in_sizes[1];

    static cudaStream_t s2 = nullptr;
    static cudaEvent_t evFork = nullptr, evJoin = nullptr;
    if (s2 == nullptr) {
        cudaStreamCreateWithFlags(&s2, cudaStreamNonBlocking);
        cudaEventCreateWithFlags(&evFork, cudaEventDisableTiming);
        cudaEventCreateWithFlags(&evJoin, cudaEventDisableTiming);
    }

    int nscan = (n + SCAN_B - 1) / SCAN_B;
    int epairs = (e + 1) / 2;

    k_detect<<<512, 256>>>(src, dst, e, n);

    cudaEventRecord(evFork, 0);
    cudaStreamWaitEvent(s2, evFork, 0);
    k_h2h<<<1024, 256, 0, s2>>>(h, n);
    cudaEventRecord(evJoin, s2);

    k_hist<<<(epairs + 255) / 256, 256>>>(dst, e, n);
    k_scan1<<<nscan, SCAN_B>>>(n);
    k_scan2<<<1, MAXPARTS>>>(nscan);
    k_fill<<<(epairs + 255) / 256, 256>>>(src, e, n);

    cudaStreamWaitEvent(0, evJoin, 0);
    k_gather<<<(n * 32 + 255) / 256, 256>>>(n);

    int ntiles = (n + MT - 1) / MT;
    size_t smem = (size_t)(128 * WP16 + MT * AP16) * sizeof(unsigned);
    cudaFuncSetAttribute(k_gemm_tc, cudaFuncAttributeMaxDynamicSharedMemorySize, (int)smem);
    k_gemm_tc<<<2 * NSM, 256, smem>>>(Wself, Wneigh, bias, out, n, ntiles);

    k_final<<<(n * (DD / 4) + 255) / 256, 256>>>(h, gamma, beta, out, n, 1.0f / (float)n);
}